// round 12
// baseline (speedup 1.0000x reference)
#include <cuda_runtime.h>
#include <cuda_bf16.h>
#include <cstdint>

// ShapeConv hybrid: bf16 mma.sync tensor path (t >= 1536) + fp32x2 FFMA2 path
// (t < 1536) running concurrently on every SMSP. Legacy mma is rate-limited at
// ~16cyc/instr (measured R3-R11); the fma pipe adds ~25% chip MAC capacity.

#define BB 32
#define CC 3
#define LL 8192
#define OO 128
#define KW 64
#define WW (LL - KW + 1)   /* 8129 valid windows */
#define KRED 192
#define APW 100            /* A pitch in 32-bit words (96 data + 4 pad) */
#define NBLK 296           /* 2 CTAs per SM, one wave */
#define NWRP (NBLK * 8)    /* 2368 warps */

#define TSPLIT 1536
#define NTWM 104           /* MMA 64-t windows: [1536, 8192) */
#define NTWF 48            /* FMA 32-t windows: [0, 1536) */
#define U_MMA (BB * 4 * NTWM)   /* 13312 */
#define U_FMA (BB * 4 * NTWF)   /* 6144 */
#define U_TOTAL (U_MMA + U_FMA) /* 19456 */

#define A_OFF  0u          /* 128*APW bf16x2 words = 51200 B */
#define P_OFF  51200u      /* 8 warps x 128 f32 prefix arrays */
#define WS_OFF 55296u      /* 128 f32: 0.5*||w_o||^2 */
#define SMEM_BYTES 55808

typedef unsigned long long ull;

__device__ unsigned int g_max[BB * OO];   // monotone-mapped maxima (zero-init)
__device__ unsigned int g_counter;        // ticket (zero-init)

__device__ __forceinline__ unsigned int f2mono(float f) {
    unsigned int u = __float_as_uint(f);
    return (u & 0x80000000u) ? ~u : (u | 0x80000000u);
}
__device__ __forceinline__ float mono2f(unsigned int m) {
    unsigned int u = (m & 0x80000000u) ? (m & 0x7fffffffu) : ~m;
    return __uint_as_float(u);
}
__device__ __forceinline__ uint32_t pack_bf2(float lo, float hi) {
    __nv_bfloat162 h = __float22bfloat162_rn(make_float2(lo, hi));
    return *(uint32_t*)&h;
}
__device__ __forceinline__ void mma_bf16(float* d, const uint32_t* a,
                                         uint32_t b0, uint32_t b1) {
    asm volatile(
        "mma.sync.aligned.m16n8k16.row.col.f32.bf16.bf16.f32 "
        "{%0,%1,%2,%3}, {%4,%5,%6,%7}, {%8,%9}, {%0,%1,%2,%3};"
        : "+f"(d[0]), "+f"(d[1]), "+f"(d[2]), "+f"(d[3])
        : "r"(a[0]), "r"(a[1]), "r"(a[2]), "r"(a[3]), "r"(b0), "r"(b1));
}
__device__ __forceinline__ void ldsm_x4(uint32_t* a, uint32_t saddr) {
    asm volatile(
        "ldmatrix.sync.aligned.m8n8.x4.shared.b16 {%0,%1,%2,%3}, [%4];"
        : "=r"(a[0]), "=r"(a[1]), "=r"(a[2]), "=r"(a[3]) : "r"(saddr));
}
__device__ __forceinline__ ull pk2u(uint32_t a, uint32_t b) {
    ull r; asm("mov.b64 %0, {%1,%2};" : "=l"(r) : "r"(a), "r"(b)); return r;
}
__device__ __forceinline__ ull pk2f(float v) {
    ull r; asm("mov.b64 %0, {%1,%2};" : "=l"(r) : "f"(v), "f"(v)); return r;
}
__device__ __forceinline__ void fma2(ull& d, ull a, ull b) {
    asm("fma.rn.f32x2 %0, %1, %2, %0;" : "+l"(d) : "l"(a), "l"(b));
}

// ---------------- warp prefix of squared sums over [t0, t0+128) --------------
template <bool EDGE>
__device__ __forceinline__ void build_prefix(const float* __restrict__ xb,
                                             int t0, float* __restrict__ Pw,
                                             int lane) {
    __syncwarp();
    int gi = t0 + 4 * lane;
    if (EDGE) gi = min(gi, LL - 4);
    float4 c0 = *(const float4*)(xb + gi);
    float4 c1 = *(const float4*)(xb + LL + gi);
    float4 c2 = *(const float4*)(xb + 2 * LL + gi);
    float s0 = c0.x * c0.x + c1.x * c1.x + c2.x * c2.x;
    float s1 = c0.y * c0.y + c1.y * c1.y + c2.y * c2.y;
    float s2 = c0.z * c0.z + c1.z * c1.z + c2.z * c2.z;
    float s3 = c0.w * c0.w + c1.w * c1.w + c2.w * c2.w;
    float e1 = s0, e2 = s0 + s1, e3 = e2 + s2, tot = e3 + s3;
    float sc = tot;
    #pragma unroll
    for (int d = 1; d < 32; d <<= 1) {
        float t = __shfl_up_sync(0xffffffffu, sc, d);
        if (lane >= d) sc += t;
    }
    float base = sc - tot;
    *(float4*)(Pw + 4 * lane) = make_float4(base, base + e1, base + e2, base + e3);
    __syncwarp();
}

// ---------------- MMA unit: 32 o x 64 t, K=192 (R10 mainloop) ----------------
template <bool EDGE>
__device__ __forceinline__ void process_mma(
    const float* __restrict__ xb, int t0, uint32_t addrA0, uint32_t addrA1,
    float* __restrict__ Pw, int b, int os, int lane, int r4, int q4)
{
    build_prefix<EDGE>(xb, t0, Pw, lane);

    float acc[2][8][4];
    #pragma unroll
    for (int mi = 0; mi < 2; ++mi)
        #pragma unroll
        for (int nf = 0; nf < 8; ++nf)
            #pragma unroll
            for (int r = 0; r < 4; ++r) acc[mi][nf][r] = 0.f;

    const int off = t0 + r4 + 2 * q4;
    #pragma unroll
    for (int c = 0; c < CC; ++c) {
        const float* xc = xb + c * LL;
        uint32_t bb[15];
        #pragma unroll
        for (int u = 0; u < 15; ++u) {
            float v0, v1;
            if (EDGE) {
                int p = off + 8 * u;
                v0 = xc[min(p, LL - 1)];
                v1 = xc[min(p + 1, LL - 1)];
            } else {
                v0 = xc[off + 8 * u];
                v1 = xc[off + 8 * u + 1];
            }
            bb[u] = pack_bf2(v0, v1);
        }
        #pragma unroll
        for (int j = 0; j < 4; ++j) {
            const uint32_t cb = (uint32_t)(c * 32 + j * 8) << 2;
            uint32_t a[2][4];
            ldsm_x4(a[0], addrA0 + cb);
            ldsm_x4(a[1], addrA1 + cb);
            #pragma unroll
            for (int nf = 0; nf < 8; ++nf) {
                uint32_t b0 = bb[2 * j + nf], b1 = bb[2 * j + nf + 1];
                mma_bf16(acc[0][nf], a[0], b0, b1);
                mma_bf16(acc[1][nf], a[1], b0, b1);
            }
        }
    }

    float mrow[4];
    #pragma unroll
    for (int r = 0; r < 4; ++r) mrow[r] = __int_as_float(0xff800000);
    #pragma unroll
    for (int mi = 0; mi < 2; ++mi)
        #pragma unroll
        for (int nf = 0; nf < 8; ++nf) {
            int n0 = nf * 8 + 2 * q4;
            float w0 = 0.5f * (Pw[n0 + 64] - Pw[n0]);
            float w1 = 0.5f * (Pw[n0 + 65] - Pw[n0 + 1]);
            if (EDGE) {
                if (t0 + n0 >= WW)     w0 = __int_as_float(0x7f800000);
                if (t0 + n0 + 1 >= WW) w1 = __int_as_float(0x7f800000);
            }
            float* d = acc[mi][nf];
            mrow[mi * 2]     = fmaxf(mrow[mi * 2],     fmaxf(d[0] - w0, d[1] - w1));
            mrow[mi * 2 + 1] = fmaxf(mrow[mi * 2 + 1], fmaxf(d[2] - w0, d[3] - w1));
        }
    #pragma unroll
    for (int r = 0; r < 4; ++r) {
        mrow[r] = fmaxf(mrow[r], __shfl_xor_sync(0xffffffffu, mrow[r], 1));
        mrow[r] = fmaxf(mrow[r], __shfl_xor_sync(0xffffffffu, mrow[r], 2));
    }
    if (q4 == 0) {
        #pragma unroll
        for (int r = 0; r < 4; ++r) {
            int row = os * 32 + (r >> 1) * 16 + (r & 1) * 8 + r4;
            atomicMax(&g_max[b * OO + row], f2mono(mrow[r]));
        }
    }
}

// ---------------- FMA unit: 32 o x 32 t, K=192, fp32x2 on fma pipe -----------
// lane = og*4+tg layout: og = lane>>2 owns o-quad, tg = lane&3 owns 8 t.
// w unpacked from the bf16 A-tile (bf16-precision w, exact fp32 x).
__device__ __forceinline__ void process_fma(
    const float* __restrict__ xb, int t0, int os,
    const uint32_t* __restrict__ A_s, float* __restrict__ Pw,
    int b, int lane)
{
    build_prefix<false>(xb, t0, Pw, lane);

    const int og  = lane >> 2;
    const int tg  = lane & 3;
    const int o0  = os * 32 + og * 4;
    const int t0g = t0 + tg * 8;

    ull acc[2][8];
    #pragma unroll
    for (int p = 0; p < 2; ++p)
        #pragma unroll
        for (int t = 0; t < 8; ++t) acc[p][t] = 0ull;

    const uint32_t* w0 = A_s + (o0 + 0) * APW;
    const uint32_t* w1 = A_s + (o0 + 1) * APW;
    const uint32_t* w2 = A_s + (o0 + 2) * APW;
    const uint32_t* w3 = A_s + (o0 + 3) * APW;

    #pragma unroll
    for (int c = 0; c < CC; ++c) {
        const float* xc = xb + c * LL + t0g;
        ull xr[8];                               // rotation: xr[(k+tj)&7]=x[k+tj]
        #pragma unroll
        for (int j = 0; j < 8; ++j) xr[j] = pk2f(xc[j]);

        const int cw = c * 32;                   // kp base for this channel
        #pragma unroll 1
        for (int kb = 0; kb < 4; ++kb) {         // 16 k per block
            const int kpb = cw + kb * 8;
            uint4 q0a = *(const uint4*)(w0 + kpb), q0b = *(const uint4*)(w0 + kpb + 4);
            uint4 q1a = *(const uint4*)(w1 + kpb), q1b = *(const uint4*)(w1 + kpb + 4);
            uint4 q2a = *(const uint4*)(w2 + kpb), q2b = *(const uint4*)(w2 + kpb + 4);
            uint4 q3a = *(const uint4*)(w3 + kpb), q3b = *(const uint4*)(w3 + kpb + 4);
            const uint32_t wq0[8] = {q0a.x,q0a.y,q0a.z,q0a.w,q0b.x,q0b.y,q0b.z,q0b.w};
            const uint32_t wq1[8] = {q1a.x,q1a.y,q1a.z,q1a.w,q1b.x,q1b.y,q1b.z,q1b.w};
            const uint32_t wq2[8] = {q2a.x,q2a.y,q2a.z,q2a.w,q2b.x,q2b.y,q2b.z,q2b.w};
            const uint32_t wq3[8] = {q3a.x,q3a.y,q3a.z,q3a.w,q3b.x,q3b.y,q3b.z,q3b.w};

            #pragma unroll
            for (int kk = 0; kk < 16; ++kk) {
                const int wi = kk >> 1;
                uint32_t u0, u1, u2, u3;
                if (kk & 1) {                    // hi bf16 -> f32 bits
                    u0 = wq0[wi] & 0xffff0000u; u1 = wq1[wi] & 0xffff0000u;
                    u2 = wq2[wi] & 0xffff0000u; u3 = wq3[wi] & 0xffff0000u;
                } else {                         // lo bf16 -> f32 bits
                    u0 = wq0[wi] << 16; u1 = wq1[wi] << 16;
                    u2 = wq2[wi] << 16; u3 = wq3[wi] << 16;
                }
                ull wp01 = pk2u(u0, u1), wp23 = pk2u(u2, u3);
                #pragma unroll
                for (int tj = 0; tj < 8; ++tj) {
                    ull xv = xr[(kk + tj) & 7];
                    fma2(acc[0][tj], wp01, xv);
                    fma2(acc[1][tj], wp23, xv);
                }
                const int k = kb * 16 + kk;
                if (k < 63) xr[kk & 7] = pk2f(xc[k + 8]);
            }
        }
    }

    // epilogue: feature = D - win, max over this lane's 8 t, reduce over tg
    float mo[4];
    #pragma unroll
    for (int r = 0; r < 4; ++r) mo[r] = __int_as_float(0xff800000);
    #pragma unroll
    for (int tj = 0; tj < 8; ++tj) {
        const int n = tg * 8 + tj;
        float wn = 0.5f * (Pw[n + 64] - Pw[n]);
        float a0, a1, a2, a3;
        asm("mov.b64 {%0,%1}, %2;" : "=f"(a0), "=f"(a1) : "l"(acc[0][tj]));
        asm("mov.b64 {%0,%1}, %2;" : "=f"(a2), "=f"(a3) : "l"(acc[1][tj]));
        mo[0] = fmaxf(mo[0], a0 - wn);
        mo[1] = fmaxf(mo[1], a1 - wn);
        mo[2] = fmaxf(mo[2], a2 - wn);
        mo[3] = fmaxf(mo[3], a3 - wn);
    }
    #pragma unroll
    for (int r = 0; r < 4; ++r) {
        mo[r] = fmaxf(mo[r], __shfl_xor_sync(0xffffffffu, mo[r], 1));
        mo[r] = fmaxf(mo[r], __shfl_xor_sync(0xffffffffu, mo[r], 2));
    }
    if (tg == 0) {
        #pragma unroll
        for (int r = 0; r < 4; ++r)
            atomicMax(&g_max[b * OO + o0 + r], f2mono(mo[r]));
    }
}

extern "C" __global__ void __launch_bounds__(256, 2)
shapeconv_fused(const float* __restrict__ xg, const float* __restrict__ wg,
                float* __restrict__ out) {
    extern __shared__ char smem[];
    uint32_t* A_s = (uint32_t*)(smem + A_OFF);     // [128][APW] bf16x2
    float*    ws  = (float*)(smem + WS_OFF);       // [128]

    const int tid  = threadIdx.x;
    const int wid  = tid >> 5;
    const int lane = tid & 31;
    const int r4   = lane >> 2;
    const int q4   = lane & 3;

    float* Pw = (float*)(smem + P_OFF) + wid * 128;   // warp-private prefix

    // ---- A staging: warp w owns o-rows [16w,16w+16); free w_norm ----
    {
        const int o0w = wid * 16;
        #pragma unroll 4
        for (int oi = 0; oi < 16; ++oi) {
            const int o = o0w + oi;
            const float2* wp = (const float2*)(wg + o * KRED);
            float2 v0 = wp[lane], v1 = wp[lane + 32], v2 = wp[lane + 64];
            uint32_t* ap = A_s + o * APW;
            ap[lane]      = pack_bf2(v0.x, v0.y);
            ap[lane + 32] = pack_bf2(v1.x, v1.y);
            ap[lane + 64] = pack_bf2(v2.x, v2.y);
            float s = v0.x * v0.x + v0.y * v0.y + v1.x * v1.x + v1.y * v1.y
                    + v2.x * v2.x + v2.y * v2.y;
            #pragma unroll
            for (int d = 16; d; d >>= 1)
                s += __shfl_xor_sync(0xffffffffu, s, d);
            if (lane == 0) ws[o] = 0.5f * s;
        }
    }
    __syncthreads();          // the ONLY block barrier before finalize

    const uint32_t Abase = (uint32_t)__cvta_generic_to_shared(A_s);
    const uint32_t laneA = (uint32_t)(((lane & 15) * APW + ((lane >> 4) << 2)) << 2);

    // ---- static interleaved unit schedule over both paths ----
    const int gw = blockIdx.x * 8 + wid;
    for (int u = gw; u < U_TOTAL; u += NWRP) {
        if (u < U_MMA) {
            const int twm = u % NTWM;
            const int r   = u / NTWM;
            const int os  = r & 3;
            const int b   = r >> 2;
            const int t0  = TSPLIT + twm * 64;
            const float* xb = xg + b * CC * LL;
            const uint32_t a0 = Abase + ((uint32_t)(os * 32 * APW) << 2) + laneA;
            const uint32_t a1 = a0 + ((16 * APW) << 2);
            if (twm == NTWM - 1)
                process_mma<true >(xb, t0, a0, a1, Pw, b, os, lane, r4, q4);
            else
                process_mma<false>(xb, t0, a0, a1, Pw, b, os, lane, r4, q4);
        } else {
            const int v   = u - U_MMA;
            const int twf = v % NTWF;
            const int r   = v / NTWF;
            const int os  = r & 3;
            const int b   = r >> 2;
            const int t0  = twf * 32;
            const float* xb = xg + b * CC * LL;
            process_fma(xb, t0, os, A_s, Pw, b, lane);
        }
    }

    // ---- last-block inline finalize ----
    __threadfence();
    __shared__ unsigned int s_last;
    if (tid == 0)
        s_last = (atomicAdd(&g_counter, 1u) == NBLK - 1u) ? 1u : 0u;
    __syncthreads();
    if (s_last) {
        for (int idx = tid; idx < BB * OO; idx += 256) {
            int o = idx & (OO - 1);
            float v = mono2f(g_max[idx]);
            out[idx] = -2.0f * (v - ws[o]);
            g_max[idx] = 0u;               // reset for next graph replay
        }
        if (tid == 0) g_counter = 0u;
    }
}

extern "C" void kernel_launch(void* const* d_in, const int* in_sizes, int n_in,
                              void* d_out, int out_size) {
    const float* x = (const float*)d_in[0];
    const float* w = (const float*)d_in[1];
    float* out = (float*)d_out;

    cudaFuncSetAttribute(shapeconv_fused,
                         cudaFuncAttributeMaxDynamicSharedMemorySize, SMEM_BYTES);
    shapeconv_fused<<<NBLK, 256, SMEM_BYTES>>>(x, w, out);
}